// round 13
// baseline (speedup 1.0000x reference)
#include <cuda_runtime.h>
#include <cuda_bf16.h>
#include <math.h>
#include <stdint.h>

// ---------------------------------------------------------------------------
// GGNN session-rec, B=512, T=50, D=100, N_NODE=100000, step=1
// R9: "convert once, copy many" — pre-split E/Y/adj to bf16 hi/lo; hio GEMM
// writes bf16 hi/lo directly. Staging in logits/adj kernels is pure copies.
// ---------------------------------------------------------------------------

#define BATCH 512
#define TSEQ  50
#define DIM   100
#define BT    (BATCH*TSEQ)      /* 25600 */
#define NOUT  99999
#define EPAD  100096            /* 782*128 */

__device__ float g_scratch[26000000];
__device__ __nv_bfloat16 g_whi[172032];
__device__ __nv_bfloat16 g_wlo[172032];
__device__ __nv_bfloat16 g_ehi[(size_t)EPAD*128];
__device__ __nv_bfloat16 g_elo[(size_t)EPAD*128];
__device__ __nv_bfloat16 g_yhi[512*128];
__device__ __nv_bfloat16 g_ylo[512*128];
__device__ __nv_bfloat16 g_aih[512*4096];
__device__ __nv_bfloat16 g_ail[512*4096];
__device__ __nv_bfloat16 g_aoh[512*4096];
__device__ __nv_bfloat16 g_aol[512*4096];
__device__ __nv_bfloat16 g_hiohi[(size_t)BT*200];
__device__ __nv_bfloat16 g_hiolo[(size_t)BT*200];

#define WO_HIO  0
#define WO_GATE 32768
#define WO_CAND 114688
#define WO_SEQ  155648

#define OFF_Z     0
#define OFF_GATES 12800000
#define OFF_REMB  17920000
#define OFF_SEQH  20480000
#define OFF_SEQ   23040000
#define OFF_LASTH 25600000
#define OFF_LAST  25651200
#define OFF_MA    25702400
#define OFF_Y1    25804800
#define OFF_BIO   25856000

__device__ __forceinline__ float sigmoidf_(float x){ return 1.f/(1.f+expf(-x)); }

__device__ __forceinline__ uint32_t pack_bf2(__nv_bfloat16 a, __nv_bfloat16 b){
  return ((uint32_t)__bfloat16_as_ushort(b)<<16) | (uint32_t)__bfloat16_as_ushort(a);
}
__device__ __forceinline__ void split4(float4 v, uint2& hi, uint2& lo){
  __nv_bfloat16 h0=__float2bfloat16(v.x), h1=__float2bfloat16(v.y),
                h2=__float2bfloat16(v.z), h3=__float2bfloat16(v.w);
  hi.x = pack_bf2(h0,h1); hi.y = pack_bf2(h2,h3);
  __nv_bfloat16 l0=__float2bfloat16(v.x-__bfloat162float(h0));
  __nv_bfloat16 l1=__float2bfloat16(v.y-__bfloat162float(h1));
  __nv_bfloat16 l2=__float2bfloat16(v.z-__bfloat162float(h2));
  __nv_bfloat16 l3=__float2bfloat16(v.w-__bfloat162float(h3));
  lo.x = pack_bf2(l0,l1); lo.y = pack_bf2(l2,l3);
}
__device__ __forceinline__ void split1(float v, __nv_bfloat16& h, __nv_bfloat16& l){
  h = __float2bfloat16(v);
  l = __float2bfloat16(v - __bfloat162float(h));
}
__device__ __forceinline__ void mma16816(float* d, uint32_t a0, uint32_t a1,
                                         uint32_t a2, uint32_t a3,
                                         uint32_t b0, uint32_t b1){
  asm volatile("mma.sync.aligned.m16n8k16.row.col.f32.bf16.bf16.f32 "
               "{%0,%1,%2,%3}, {%4,%5,%6,%7}, {%8,%9}, {%0,%1,%2,%3};"
               : "+f"(d[0]), "+f"(d[1]), "+f"(d[2]), "+f"(d[3])
               : "r"(a0), "r"(a1), "r"(a2), "r"(a3), "r"(b0), "r"(b1));
}
__device__ __forceinline__ uint32_t lds32(const __nv_bfloat16* p){
  return *(const uint32_t*)p;
}

// --------------------------- weight prep -----------------------------------
__global__ void k_prep(const float* __restrict__ W_in, const float* __restrict__ W_out,
                       const float* __restrict__ Ggate, const float* __restrict__ Gcand,
                       const float* __restrict__ w2,
                       const float* __restrict__ b_in, const float* __restrict__ b_out,
                       __nv_bfloat16* __restrict__ whi, __nv_bfloat16* __restrict__ wlo,
                       float* __restrict__ bio){
  int i = blockIdx.x*256 + threadIdx.x;
  if (i < 172032){
    float v = 0.f;
    if (i < 32768){
      int n = i>>7, k = i&127;
      if (k < 100) v = (n < 100) ? W_in[k*100+n] : W_out[k*100+(n-100)];
    } else if (i < 114688){
      int j = i-32768; int n = j/320, k = j - n*320;
      if (k < 300) v = Ggate[k*200+n];
    } else if (i < 155648){
      int j = i-114688; int n = j/320, k = j - n*320;
      if (k < 300) v = Gcand[k*100+n];
    } else {
      int j = i-155648; int n = j>>7, k = j&127;
      if (k < 100) v = w2[k*100+n];
    }
    __nv_bfloat16 h = __float2bfloat16(v);
    whi[i] = h;
    wlo[i] = __float2bfloat16(v - __bfloat162float(h));
  } else if (i < 172232){
    int j = i-172032;
    bio[j] = (j < 100) ? b_in[j] : b_out[j-100];
  }
}

// --------------------------- one-time bf16 pre-splits ----------------------
__global__ void k_split_e(const float* __restrict__ emb,
                          __nv_bfloat16* __restrict__ ehi, __nv_bfloat16* __restrict__ elo){
  size_t i = (size_t)blockIdx.x*256 + threadIdx.x;
  if (i >= (size_t)EPAD*128) return;
  int r = (int)(i>>7), c = (int)(i&127);
  float v = 0.f;
  if (r < NOUT && c < DIM) v = emb[(size_t)(r+1)*DIM + c];
  __nv_bfloat16 h, l; split1(v, h, l);
  ehi[i] = h; elo[i] = l;
}
__global__ void k_split_y(const float* __restrict__ y1,
                          __nv_bfloat16* __restrict__ yhi, __nv_bfloat16* __restrict__ ylo){
  int i = blockIdx.x*256 + threadIdx.x;
  if (i >= 512*128) return;
  int r = i>>7, c = i&127;
  float v = (c < DIM) ? y1[r*DIM + c] : 0.f;
  __nv_bfloat16 h, l; split1(v, h, l);
  yhi[i] = h; ylo[i] = l;
}
// adj pre-split to padded 64x64 tiles per batch
__global__ void k_split_adj(const float* __restrict__ adj_in, const float* __restrict__ adj_out,
                            __nv_bfloat16* __restrict__ aih, __nv_bfloat16* __restrict__ ail,
                            __nv_bfloat16* __restrict__ aoh, __nv_bfloat16* __restrict__ aol){
  int i = blockIdx.x*256 + threadIdx.x;
  if (i >= 512*4096) return;
  int b = i>>12, r = i&4095, t = r>>6, s = r&63;
  float vi = 0.f, vo = 0.f;
  if (t < TSEQ && s < TSEQ){
    vi = adj_in [(size_t)b*2500 + t*TSEQ + s];
    vo = adj_out[(size_t)b*2500 + t*TSEQ + s];
  }
  __nv_bfloat16 h, l;
  split1(vi, h, l); aih[i] = h; ail[i] = l;
  split1(vo, h, l); aoh[i] = h; aol[i] = l;
}

// --------------------------- gather: h -> z[:,200:300] ---------------------
__global__ void k_gather(const float* __restrict__ emb, const int* __restrict__ item,
                         float* __restrict__ z){
  int i = blockIdx.x*256 + threadIdx.x;
  if (i >= BT*DIM) return;
  int row = i/DIM, col = i - row*DIM;
  z[row*300 + 200 + col] = __ldg(&emb[(size_t)item[row]*DIM + col]);
}

// --------------------------- adjacency einsums on tensor cores -------------
#define AS 72
#define ADJ_AIH 0
#define ADJ_AIL (64*AS)
#define ADJ_AOH (2*64*AS)
#define ADJ_AOL (3*64*AS)
#define ADJ_B0  (4*64*AS)
#define ADJ_BIH (ADJ_B0)
#define ADJ_BIL (ADJ_B0 + 128*AS)
#define ADJ_BOH (ADJ_B0 + 2*128*AS)
#define ADJ_BOL (ADJ_B0 + 3*128*AS)
#define ADJ_SMEM_UNITS (4*64*AS + 4*128*AS)
#define ADJ_SMEM_BYTES (ADJ_SMEM_UNITS*2)

__global__ void __launch_bounds__(256, 2) k_adj_tc(
    const __nv_bfloat16* __restrict__ aih, const __nv_bfloat16* __restrict__ ail,
    const __nv_bfloat16* __restrict__ aoh, const __nv_bfloat16* __restrict__ aol,
    const __nv_bfloat16* __restrict__ hioh, const __nv_bfloat16* __restrict__ hiol,
    float* __restrict__ z){
  extern __shared__ __nv_bfloat16 sma[];
  int b = blockIdx.x, tid = threadIdx.x;

  // zero-fill B region (pad rows d>=100 and cols s>=50 must be 0)
  {
    uint4* p = (uint4*)(sma + ADJ_B0);
    for (int i = tid; i < (4*128*AS)/8; i += 256) p[i] = make_uint4(0,0,0,0);
  }
  // adj tiles: pure vector copies (pre-padded)
  {
    const uint4* si = (const uint4*)(aih + (size_t)b*4096);
    const uint4* sl = (const uint4*)(ail + (size_t)b*4096);
    const uint4* so = (const uint4*)(aoh + (size_t)b*4096);
    const uint4* sq = (const uint4*)(aol + (size_t)b*4096);
    for (int i = tid; i < 512; i += 256){
      int row = i>>3, q = i&7;
      int d = row*AS + q*8;
      *(uint4*)(sma + ADJ_AIH + d) = si[i];
      *(uint4*)(sma + ADJ_AIL + d) = sl[i];
      *(uint4*)(sma + ADJ_AOH + d) = so[i];
      *(uint4*)(sma + ADJ_AOL + d) = sq[i];
    }
  }
  __syncthreads();
  // hio transposed copy: [s][d] -> [d][s], no conversion (pre-split bf16)
  for (int i = tid; i < 5000; i += 256){
    int s = i/100, dp = i - s*100, d = dp*2;
    uint32_t vh = *(const uint32_t*)(hioh + (size_t)(b*TSEQ+s)*200 + d);
    uint32_t vl = *(const uint32_t*)(hiol + (size_t)(b*TSEQ+s)*200 + d);
    int base = (d < 100) ? ADJ_BIH : ADJ_BOH;
    int basl = (d < 100) ? ADJ_BIL : ADJ_BOL;
    int dd = (d < 100) ? d : d-100;
    sma[base + dd*AS + s]     = __ushort_as_bfloat16((unsigned short)(vh & 0xffff));
    sma[base + (dd+1)*AS + s] = __ushort_as_bfloat16((unsigned short)(vh >> 16));
    sma[basl + dd*AS + s]     = __ushort_as_bfloat16((unsigned short)(vl & 0xffff));
    sma[basl + (dd+1)*AS + s] = __ushort_as_bfloat16((unsigned short)(vl >> 16));
  }
  __syncthreads();

  int wid = tid>>5, lane = tid&31;
  int e  = wid>>2;
  int n0 = (wid&3)*32;
  int qr = lane>>2, qc = (lane&3)*2;

  const __nv_bfloat16* Ah = sma + (e ? ADJ_AOH : ADJ_AIH);
  const __nv_bfloat16* Al = sma + (e ? ADJ_AOL : ADJ_AIL);
  const __nv_bfloat16* Bh = sma + (e ? ADJ_BOH : ADJ_BIH);
  const __nv_bfloat16* Bl = sma + (e ? ADJ_BOL : ADJ_BIL);

  float acc[4][4][4];
  #pragma unroll
  for (int mt=0;mt<4;mt++)
    #pragma unroll
    for (int nt=0;nt<4;nt++)
      #pragma unroll
      for (int j=0;j<4;j++) acc[mt][nt][j]=0.f;

  #pragma unroll
  for (int ks=0; ks<4; ks++){
    int kk = ks*16 + qc;
    uint32_t ah[4][4], al[4][4];
    #pragma unroll
    for (int mt=0; mt<4; mt++){
      int r = mt*16 + qr;
      ah[mt][0]=lds32(Ah + r*AS + kk);     ah[mt][1]=lds32(Ah + (r+8)*AS + kk);
      ah[mt][2]=lds32(Ah + r*AS + kk+8);   ah[mt][3]=lds32(Ah + (r+8)*AS + kk+8);
      al[mt][0]=lds32(Al + r*AS + kk);     al[mt][1]=lds32(Al + (r+8)*AS + kk);
      al[mt][2]=lds32(Al + r*AS + kk+8);   al[mt][3]=lds32(Al + (r+8)*AS + kk+8);
    }
    #pragma unroll
    for (int nt=0; nt<4; nt++){
      int n = n0 + nt*8 + qr;
      uint32_t bh0 = lds32(Bh + n*AS + kk), bh1 = lds32(Bh + n*AS + kk+8);
      uint32_t bl0 = lds32(Bl + n*AS + kk), bl1 = lds32(Bl + n*AS + kk+8);
      #pragma unroll
      for (int mt=0; mt<4; mt++){
        mma16816(acc[mt][nt], ah[mt][0],ah[mt][1],ah[mt][2],ah[mt][3], bh0,bh1);
        mma16816(acc[mt][nt], al[mt][0],al[mt][1],al[mt][2],al[mt][3], bh0,bh1);
        mma16816(acc[mt][nt], ah[mt][0],ah[mt][1],ah[mt][2],ah[mt][3], bl0,bl1);
      }
    }
  }

  int cb = e*100;
  #pragma unroll
  for (int mt=0; mt<4; mt++){
    int t0 = mt*16 + qr;
    #pragma unroll
    for (int nt=0; nt<4; nt++){
      int d = n0 + nt*8 + qc;
      if (d+1 < 100){
        if (t0 < TSEQ){
          float* p = z + (size_t)(b*TSEQ+t0)*300 + cb + d;
          p[0] = acc[mt][nt][0]; p[1] = acc[mt][nt][1];
        }
        if (t0+8 < TSEQ){
          float* p = z + (size_t)(b*TSEQ+t0+8)*300 + cb + d;
          p[0] = acc[mt][nt][2]; p[1] = acc[mt][nt][3];
        }
      }
    }
  }
}

// --------------------------- small FFMA SGEMM ------------------------------
__global__ void k_sgemm(const float* __restrict__ A, const float* __restrict__ Bm,
                        const float* __restrict__ bias, float* __restrict__ C,
                        int M, int N, int K, int act){
  __shared__ float As[16][65];
  __shared__ float Bs[16][65];
  int tid = threadIdx.x;
  int tx = tid & 15, ty = tid >> 4;
  int m0 = blockIdx.y*64, n0 = blockIdx.x*64;
  float acc[4][4] = {};
  for (int k0=0;k0<K;k0+=16){
    for (int idx=tid; idx<1024; idx+=256){
      int m = idx>>4, k = idx&15;
      As[k][m] = (k0+k < K) ? A[(size_t)(m0+m)*K + k0+k] : 0.f;
    }
    for (int idx=tid; idx<1024; idx+=256){
      int k = idx>>6, n = idx&63;
      Bs[k][n] = (k0+k < K && n0+n < N) ? Bm[(size_t)(k0+k)*N + n0+n] : 0.f;
    }
    __syncthreads();
    #pragma unroll
    for (int kk=0;kk<16;kk++){
      float a[4], bb[4];
      #pragma unroll
      for (int i=0;i<4;i++) a[i] = As[kk][ty+16*i];
      #pragma unroll
      for (int j=0;j<4;j++) bb[j] = Bs[kk][tx+16*j];
      #pragma unroll
      for (int i=0;i<4;i++)
        #pragma unroll
        for (int j=0;j<4;j++)
          acc[i][j] += a[i]*bb[j];
    }
    __syncthreads();
  }
  #pragma unroll
  for (int j=0;j<4;j++){
    int n = n0 + tx + 16*j;
    if (n >= N) continue;
    float bv = bias ? bias[n] : 0.f;
    #pragma unroll
    for (int i=0;i<4;i++){
      int m = m0 + ty + 16*i;
      float v = acc[i][j] + bv;
      if (act==1)      v = sigmoidf_(v);
      else if (act==2) v = tanhf(v);
      C[(size_t)m*N + n] = v;
    }
  }
}

// --------------------------- seq_h / last_h gather -------------------------
__global__ void k_seqprep(const float* __restrict__ mask, const int* __restrict__ alias,
                          const float* __restrict__ remb,
                          float* __restrict__ seqh, float* __restrict__ lasth){
  __shared__ int al[TSEQ];
  __shared__ int lid_s;
  int b = blockIdx.x, tid = threadIdx.x;
  if (tid < TSEQ) al[tid] = alias[b*TSEQ+tid];
  __syncthreads();
  if (tid == 0){
    float s = 0.f;
    for (int t=0;t<TSEQ;t++) s += mask[b*TSEQ+t];
    int r = (int)(s + 0.5f) - 1;
    if (r < 0) r = 0; if (r >= TSEQ) r = TSEQ-1;
    lid_s = al[r];
  }
  __syncthreads();
  for (int i=tid;i<TSEQ*DIM;i+=128){
    int t = i/DIM, j = i - t*DIM;
    seqh[(size_t)(b*TSEQ+t)*DIM + j] = remb[(size_t)(b*TSEQ + al[t])*DIM + j];
  }
  if (tid < DIM) lasth[b*DIM+tid] = remb[(size_t)(b*TSEQ + lid_s)*DIM + tid];
}

// --------------------------- attention readout -----------------------------
__global__ void k_attn(const float* __restrict__ last, const float* __restrict__ seq,
                       const float* __restrict__ seqh, const float* __restrict__ nb,
                       const float* __restrict__ v, const float* __restrict__ mask,
                       float* __restrict__ ma){
  __shared__ float coef[TSEQ], ls[DIM], vs[DIM], bs[DIM];
  int b = blockIdx.x, tid = threadIdx.x;
  if (tid < DIM){ ls[tid]=last[b*DIM+tid]; vs[tid]=v[tid]; bs[tid]=nb[tid]; }
  __syncthreads();
  int w = tid >> 5, lane = tid & 31;
  for (int t=w; t<TSEQ; t+=8){
    const float* srow = seq + (size_t)(b*TSEQ+t)*DIM;
    float p = 0.f;
    for (int j=lane; j<DIM; j+=32){
      float mv = sigmoidf_(ls[j]+srow[j]+bs[j]);
      p += mv*vs[j];
    }
    #pragma unroll
    for (int o=16;o;o>>=1) p += __shfl_xor_sync(0xffffffffu, p, o);
    if (lane==0) coef[t] = p * mask[b*TSEQ+t];
  }
  __syncthreads();
  if (tid < DIM){
    float s = 0.f;
    #pragma unroll
    for (int t=0;t<TSEQ;t++) s += coef[t]*seqh[(size_t)(b*TSEQ+t)*DIM+tid];
    ma[b*200+tid]       = s;
    ma[b*200+100+tid]   = ls[tid];
  }
}

// --------------------------- generic tc GEMM (inline A split) --------------
// emode 0 none, 1 sigmoid, 3 GRU fuse, 4 write bf16 hi/lo (hio producer)
#define LS2 72
#define GEMM_SMEM (4*128*LS2*2)

__global__ void __launch_bounds__(256, 2) k_gemm_tc(
    const float* __restrict__ A, const float* __restrict__ Gt,
    const __nv_bfloat16* __restrict__ Whi, const __nv_bfloat16* __restrict__ Wlo,
    const float* __restrict__ bias, float* __restrict__ C,
    __nv_bfloat16* __restrict__ Cbh, __nv_bfloat16* __restrict__ Cbl,
    int Astride, int Ka, int Kp, int Nact, int amode, int emode){
  extern __shared__ __nv_bfloat16 smg[];
  __nv_bfloat16* sAh = smg;
  __nv_bfloat16* sAl = smg + 128*LS2;
  __nv_bfloat16* sWh = smg + 2*128*LS2;
  __nv_bfloat16* sWl = smg + 3*128*LS2;
  int tid = threadIdx.x;
  int n0 = blockIdx.x*128, y0 = blockIdx.y*128;
  int wid = tid>>5, lane = tid&31;
  int wm = wid&3, wn = wid>>2;
  int qr = lane>>2, qc = (lane&3)*2;

  float acc[2][8][4];
  #pragma unroll
  for (int mt=0;mt<2;mt++)
    #pragma unroll
    for (int nt=0;nt<8;nt++)
      #pragma unroll
      for (int j=0;j<4;j++) acc[mt][nt][j]=0.f;

  int nchunk = Kp >> 6;
  for (int kc=0; kc<nchunk; kc++){
    #pragma unroll
    for (int s=0;s<8;s++){
      int idx = s*256+tid;
      int row = idx>>4, q = idx&15;
      int col = kc*64 + q*4;
      float4 v = make_float4(0.f,0.f,0.f,0.f);
      if (amode == 0){
        if (col < Ka) v = *(const float4*)(A + (size_t)(y0+row)*Astride + col);
      } else {
        if (col < 200) v = *(const float4*)(A + (size_t)(y0+row)*300 + col);
        else if (col < 300){
          float4 zv = *(const float4*)(A + (size_t)(y0+row)*300 + col);
          float4 gv = *(const float4*)(Gt + (size_t)(y0+row)*200 + (col-200));
          v = make_float4(zv.x*gv.x, zv.y*gv.y, zv.z*gv.z, zv.w*gv.w);
        }
      }
      uint2 hi, lo; split4(v, hi, lo);
      *(uint2*)(sAh + row*LS2 + q*4) = hi;
      *(uint2*)(sAl + row*LS2 + q*4) = lo;
    }
    #pragma unroll
    for (int s=0;s<4;s++){
      int idx = s*256+tid;
      int row = idx>>3, c8 = idx&7;
      size_t g = (size_t)(n0+row)*Kp + kc*64 + c8*8;
      *(uint4*)(sWh + row*LS2 + c8*8) = *(const uint4*)(Whi + g);
      *(uint4*)(sWl + row*LS2 + c8*8) = *(const uint4*)(Wlo + g);
    }
    __syncthreads();
    #pragma unroll
    for (int ks=0; ks<4; ks++){
      int kk = ks*16 + qc;
      uint32_t ah[2][4], al[2][4];
      #pragma unroll
      for (int mt=0; mt<2; mt++){
        int r = wm*32 + mt*16 + qr;
        const __nv_bfloat16* p0h = sAh + r*LS2;
        const __nv_bfloat16* p1h = sAh + (r+8)*LS2;
        const __nv_bfloat16* p0l = sAl + r*LS2;
        const __nv_bfloat16* p1l = sAl + (r+8)*LS2;
        ah[mt][0]=lds32(p0h+kk); ah[mt][1]=lds32(p1h+kk);
        ah[mt][2]=lds32(p0h+kk+8); ah[mt][3]=lds32(p1h+kk+8);
        al[mt][0]=lds32(p0l+kk); al[mt][1]=lds32(p1l+kk);
        al[mt][2]=lds32(p0l+kk+8); al[mt][3]=lds32(p1l+kk+8);
      }
      #pragma unroll
      for (int nt=0; nt<8; nt++){
        int n = wn*64 + nt*8 + qr;
        const __nv_bfloat16* pbh = sWh + n*LS2 + kk;
        const __nv_bfloat16* pbl = sWl + n*LS2 + kk;
        uint32_t bh0 = lds32(pbh), bh1 = lds32(pbh+8);
        uint32_t bl0 = lds32(pbl), bl1 = lds32(pbl+8);
        #pragma unroll
        for (int mt=0; mt<2; mt++){
          mma16816(acc[mt][nt], ah[mt][0],ah[mt][1],ah[mt][2],ah[mt][3], bh0,bh1);
          mma16816(acc[mt][nt], al[mt][0],al[mt][1],al[mt][2],al[mt][3], bh0,bh1);
          mma16816(acc[mt][nt], ah[mt][0],ah[mt][1],ah[mt][2],ah[mt][3], bl0,bl1);
        }
      }
    }
    __syncthreads();
  }

  #pragma unroll
  for (int mt=0; mt<2; mt++){
    int y = y0 + wm*32 + mt*16 + qr;
    #pragma unroll
    for (int nt=0; nt<8; nt++){
      #pragma unroll
      for (int half=0; half<2; half++){
        int nn = n0 + wn*64 + nt*8 + qc + half;
        if (nn >= Nact) continue;
        float bv = bias ? bias[nn] : 0.f;
        float v0 = acc[mt][nt][half]   + bv;
        float v1 = acc[mt][nt][2+half] + bv;
        if (emode==1){ v0 = sigmoidf_(v0); v1 = sigmoidf_(v1); }
        else if (emode==3){
          v0 = tanhf(v0); v1 = tanhf(v1);
          float u0 = Gt[(size_t)y*200 + 100 + nn];
          float u1 = Gt[(size_t)(y+8)*200 + 100 + nn];
          float h0 = A[(size_t)y*300 + 200 + nn];
          float h1 = A[(size_t)(y+8)*300 + 200 + nn];
          v0 = u0*h0 + (1.f-u0)*v0;
          v1 = u1*h1 + (1.f-u1)*v1;
        }
        if (emode==4){
          __nv_bfloat16 h, l;
          split1(v0, h, l); Cbh[(size_t)y*Nact + nn] = h; Cbl[(size_t)y*Nact + nn] = l;
          split1(v1, h, l); Cbh[(size_t)(y+8)*Nact + nn] = h; Cbl[(size_t)(y+8)*Nact + nn] = l;
        } else {
          C[(size_t)y*Nact + nn] = v0;
          C[(size_t)(y+8)*Nact + nn] = v1;
        }
      }
    }
  }
}

// --------------------------- logits GEMM (pre-split operands) --------------
#define LOGITS_SMEM (4*128*LS2*2)

__global__ void __launch_bounds__(256, 2) k_logits_mma(
    const __nv_bfloat16* __restrict__ Ehi, const __nv_bfloat16* __restrict__ Elo,
    const __nv_bfloat16* __restrict__ Yhi, const __nv_bfloat16* __restrict__ Ylo,
    float* __restrict__ out){
  extern __shared__ __nv_bfloat16 smb[];
  __nv_bfloat16* sYh = smb;
  __nv_bfloat16* sYl = smb + 128*LS2;
  __nv_bfloat16* sEh = smb + 2*128*LS2;
  __nv_bfloat16* sEl = smb + 3*128*LS2;

  int tid = threadIdx.x;
  int e0 = blockIdx.x*128;
  int y0 = blockIdx.y*128;
  int wid = tid>>5, lane = tid&31;
  int wm = wid&3, wn = wid>>2;
  int qr = lane>>2, qc = (lane&3)*2;

  float acc[2][8][4];
  #pragma unroll
  for (int mt=0;mt<2;mt++)
    #pragma unroll
    for (int nt=0;nt<8;nt++)
      #pragma unroll
      for (int j=0;j<4;j++) acc[mt][nt][j] = 0.f;

  #pragma unroll
  for (int kc=0; kc<2; kc++){
    // pure uint4 copies: 4 arrays x 1024 uint4
    #pragma unroll
    for (int s=0;s<4;s++){
      int idx = s*256+tid;
      int row = idx>>3, q = idx&7;
      size_t gE = (size_t)(e0+row)*128 + kc*64 + q*8;
      size_t gY = (size_t)(y0+row)*128 + kc*64 + q*8;
      int so = row*LS2 + q*8;
      *(uint4*)(sEh + so) = *(const uint4*)(Ehi + gE);
      *(uint4*)(sEl + so) = *(const uint4*)(Elo + gE);
      *(uint4*)(sYh + so) = *(const uint4*)(Yhi + gY);
      *(uint4*)(sYl + so) = *(const uint4*)(Ylo + gY);
    }
    __syncthreads();
    #pragma unroll
    for (int ks=0; ks<4; ks++){
      int kk = ks*16 + qc;
      uint32_t ah[2][4], al[2][4];
      #pragma unroll
      for (int mt=0; mt<2; mt++){
        int r = wm*32 + mt*16 + qr;
        const __nv_bfloat16* p0h = sYh + r*LS2;
        const __nv_bfloat16* p1h = sYh + (r+8)*LS2;
        const __nv_bfloat16* p0l = sYl + r*LS2;
        const __nv_bfloat16* p1l = sYl + (r+8)*LS2;
        ah[mt][0]=lds32(p0h+kk); ah[mt][1]=lds32(p1h+kk);
        ah[mt][2]=lds32(p0h+kk+8); ah[mt][3]=lds32(p1h+kk+8);
        al[mt][0]=lds32(p0l+kk); al[mt][1]=lds32(p1l+kk);
        al[mt][2]=lds32(p0l+kk+8); al[mt][3]=lds32(p1l+kk+8);
      }
      #pragma unroll
      for (int nt=0; nt<8; nt++){
        int n = wn*64 + nt*8 + qr;
        const __nv_bfloat16* pbh = sEh + n*LS2 + kk;
        const __nv_bfloat16* pbl = sEl + n*LS2 + kk;
        uint32_t bh0 = lds32(pbh), bh1 = lds32(pbh+8);
        uint32_t bl0 = lds32(pbl), bl1 = lds32(pbl+8);
        #pragma unroll
        for (int mt=0; mt<2; mt++){
          mma16816(acc[mt][nt], ah[mt][0],ah[mt][1],ah[mt][2],ah[mt][3], bh0,bh1);
          mma16816(acc[mt][nt], al[mt][0],al[mt][1],al[mt][2],al[mt][3], bh0,bh1);
          mma16816(acc[mt][nt], ah[mt][0],ah[mt][1],ah[mt][2],ah[mt][3], bl0,bl1);
        }
      }
    }
    __syncthreads();
  }

  #pragma unroll
  for (int mt=0; mt<2; mt++){
    int y = y0 + wm*32 + mt*16 + qr;
    #pragma unroll
    for (int nt=0; nt<8; nt++){
      int e = e0 + wn*64 + nt*8 + qc;
      float* po = out + (size_t)y*NOUT + e;
      if (e   < NOUT){ po[0] = acc[mt][nt][0]; po[(size_t)8*NOUT] = acc[mt][nt][2]; }
      if (e+1 < NOUT){ po[1] = acc[mt][nt][1]; po[(size_t)8*NOUT+1] = acc[mt][nt][3]; }
    }
  }
}

// ---------------------------------------------------------------------------
extern "C" void kernel_launch(void* const* d_in, const int* in_sizes, int n_in,
                              void* d_out, int out_size){
  const float* adj_in  = (const float*)d_in[0];
  const float* adj_out = (const float*)d_in[1];
  const float* maskp   = (const float*)d_in[2];
  const int*   item    = (const int*)d_in[3];
  const int*   alias   = (const int*)d_in[4];
  int o = (n_in >= 20 && in_sizes[5] == 1) ? 6 : 5;
  const float* emb   = (const float*)d_in[o+0];
  const float* W_in  = (const float*)d_in[o+1];
  const float* b_in  = (const float*)d_in[o+2];
  const float* W_out = (const float*)d_in[o+3];
  const float* b_out = (const float*)d_in[o+4];
  const float* Ggate = (const float*)d_in[o+5];
  const float* gb    = (const float*)d_in[o+6];
  const float* Gcand = (const float*)d_in[o+7];
  const float* cb    = (const float*)d_in[o+8];
  const float* w1    = (const float*)d_in[o+9];
  const float* w2    = (const float*)d_in[o+10];
  const float* vv    = (const float*)d_in[o+11];
  const float* nb    = (const float*)d_in[o+12];
  const float* Bmat  = (const float*)d_in[o+13];
  float* out = (float*)d_out;
  (void)out_size;

  float* sc = nullptr;
  cudaGetSymbolAddress((void**)&sc, g_scratch);
  __nv_bfloat16 *whi=nullptr, *wlo=nullptr, *ehi=nullptr, *elo=nullptr;
  __nv_bfloat16 *yhi=nullptr, *ylo=nullptr;
  __nv_bfloat16 *aih=nullptr, *ail=nullptr, *aoh=nullptr, *aol=nullptr;
  __nv_bfloat16 *hiohi=nullptr, *hiolo=nullptr;
  cudaGetSymbolAddress((void**)&whi, g_whi);
  cudaGetSymbolAddress((void**)&wlo, g_wlo);
  cudaGetSymbolAddress((void**)&ehi, g_ehi);
  cudaGetSymbolAddress((void**)&elo, g_elo);
  cudaGetSymbolAddress((void**)&yhi, g_yhi);
  cudaGetSymbolAddress((void**)&ylo, g_ylo);
  cudaGetSymbolAddress((void**)&aih, g_aih);
  cudaGetSymbolAddress((void**)&ail, g_ail);
  cudaGetSymbolAddress((void**)&aoh, g_aoh);
  cudaGetSymbolAddress((void**)&aol, g_aol);
  cudaGetSymbolAddress((void**)&hiohi, g_hiohi);
  cudaGetSymbolAddress((void**)&hiolo, g_hiolo);

  float* z     = sc + OFF_Z;
  float* gates = sc + OFF_GATES;
  float* remb  = sc + OFF_REMB;
  float* seqh  = sc + OFF_SEQH;
  float* seq   = sc + OFF_SEQ;
  float* lasth = sc + OFF_LASTH;
  float* lastT = sc + OFF_LAST;
  float* ma    = sc + OFF_MA;
  float* y1    = sc + OFF_Y1;
  float* bio   = sc + OFF_BIO;

  cudaFuncSetAttribute(k_adj_tc, cudaFuncAttributeMaxDynamicSharedMemorySize, ADJ_SMEM_BYTES);
  cudaFuncSetAttribute(k_gemm_tc, cudaFuncAttributeMaxDynamicSharedMemorySize, GEMM_SMEM);
  cudaFuncSetAttribute(k_logits_mma, cudaFuncAttributeMaxDynamicSharedMemorySize, LOGITS_SMEM);

  // one-time preps
  k_prep<<<(172232+255)/256,256>>>(W_in, W_out, Ggate, Gcand, w2, b_in, b_out, whi, wlo, bio);
  k_split_e<<<(int)(((size_t)EPAD*128 + 255)/256), 256>>>(emb, ehi, elo);
  k_split_adj<<<(512*4096+255)/256,256>>>(adj_in, adj_out, aih, ail, aoh, aol);

  // pipeline
  k_gather<<<(BT*DIM+255)/256, 256>>>(emb, item, z);
  // hio (bf16 hi/lo) = [h@W_in+b_in, h@W_out+b_out]
  k_gemm_tc<<<dim3(2,200),256,GEMM_SMEM>>>(z+200, nullptr, whi+WO_HIO, wlo+WO_HIO,
                                           bio, nullptr, hiohi, hiolo, 300, 100, 128, 200, 0, 4);
  k_adj_tc<<<BATCH,256,ADJ_SMEM_BYTES>>>(aih, ail, aoh, aol, hiohi, hiolo, z);
  k_gemm_tc<<<dim3(2,200),256,GEMM_SMEM>>>(z, nullptr, whi+WO_GATE, wlo+WO_GATE,
                                           gb, gates, nullptr, nullptr, 300, 300, 320, 200, 0, 1);
  k_gemm_tc<<<dim3(1,200),256,GEMM_SMEM>>>(z, gates, whi+WO_CAND, wlo+WO_CAND,
                                           cb, remb, nullptr, nullptr, 300, 300, 320, 100, 1, 3);
  k_seqprep<<<BATCH,128>>>(maskp, alias, remb, seqh, lasth);
  k_gemm_tc<<<dim3(1,200),256,GEMM_SMEM>>>(seqh, nullptr, whi+WO_SEQ, wlo+WO_SEQ,
                                           nullptr, seq, nullptr, nullptr, 100, 100, 128, 100, 0, 0);
  k_sgemm<<<dim3(2,8),256>>>(lasth, w1, nullptr, lastT, 512, DIM, DIM, 0);
  k_attn<<<BATCH,256>>>(lastT, seq, seqh, nb, vv, maskp, ma);
  k_sgemm<<<dim3(2,8),256>>>(ma, Bmat, nullptr, y1, 512, DIM, 200, 0);
  k_split_y<<<256,256>>>(y1, yhi, ylo);
  k_logits_mma<<<dim3(EPAD/128, 4), 256, LOGITS_SMEM>>>(ehi, elo, yhi, ylo, out);
}

// round 14
// speedup vs baseline: 1.0415x; 1.0415x over previous
#include <cuda_runtime.h>
#include <cuda_bf16.h>
#include <math.h>
#include <stdint.h>

// ---------------------------------------------------------------------------
// GGNN session-rec, B=512, T=50, D=100, N_NODE=100000, step=1
// R14: R8 base (best: 534.8us) + hio produced as bf16 hi/lo (adj stages by
// copy), vectorized gather/seqprep, lasth@w1 fused into attn. 11 launches.
// ---------------------------------------------------------------------------

#define BATCH 512
#define TSEQ  50
#define DIM   100
#define BT    (BATCH*TSEQ)      /* 25600 */
#define NOUT  99999
#define EPAD  100096            /* 782*128 */

__device__ float g_scratch[26000000];
__device__ __nv_bfloat16 g_whi[172032];
__device__ __nv_bfloat16 g_wlo[172032];
__device__ __nv_bfloat16 g_hiohi[(size_t)BT*200];
__device__ __nv_bfloat16 g_hiolo[(size_t)BT*200];

#define WO_HIO  0
#define WO_GATE 32768
#define WO_CAND 114688
#define WO_SEQ  155648

#define OFF_Z     0
#define OFF_GATES 12800000
#define OFF_REMB  17920000
#define OFF_SEQH  20480000
#define OFF_SEQ   23040000
#define OFF_LASTH 25600000
#define OFF_MA    25702400
#define OFF_Y1    25804800
#define OFF_BIO   25856000

__device__ __forceinline__ float sigmoidf_(float x){ return 1.f/(1.f+expf(-x)); }

__device__ __forceinline__ uint32_t pack_bf2(__nv_bfloat16 a, __nv_bfloat16 b){
  return ((uint32_t)__bfloat16_as_ushort(b)<<16) | (uint32_t)__bfloat16_as_ushort(a);
}
__device__ __forceinline__ void split4(float4 v, uint2& hi, uint2& lo){
  __nv_bfloat16 h0=__float2bfloat16(v.x), h1=__float2bfloat16(v.y),
                h2=__float2bfloat16(v.z), h3=__float2bfloat16(v.w);
  hi.x = pack_bf2(h0,h1); hi.y = pack_bf2(h2,h3);
  __nv_bfloat16 l0=__float2bfloat16(v.x-__bfloat162float(h0));
  __nv_bfloat16 l1=__float2bfloat16(v.y-__bfloat162float(h1));
  __nv_bfloat16 l2=__float2bfloat16(v.z-__bfloat162float(h2));
  __nv_bfloat16 l3=__float2bfloat16(v.w-__bfloat162float(h3));
  lo.x = pack_bf2(l0,l1); lo.y = pack_bf2(l2,l3);
}
__device__ __forceinline__ void split1(float v, __nv_bfloat16& h, __nv_bfloat16& l){
  h = __float2bfloat16(v);
  l = __float2bfloat16(v - __bfloat162float(h));
}
__device__ __forceinline__ void mma16816(float* d, uint32_t a0, uint32_t a1,
                                         uint32_t a2, uint32_t a3,
                                         uint32_t b0, uint32_t b1){
  asm volatile("mma.sync.aligned.m16n8k16.row.col.f32.bf16.bf16.f32 "
               "{%0,%1,%2,%3}, {%4,%5,%6,%7}, {%8,%9}, {%0,%1,%2,%3};"
               : "+f"(d[0]), "+f"(d[1]), "+f"(d[2]), "+f"(d[3])
               : "r"(a0), "r"(a1), "r"(a2), "r"(a3), "r"(b0), "r"(b1));
}
__device__ __forceinline__ uint32_t lds32(const __nv_bfloat16* p){
  return *(const uint32_t*)p;
}

// --------------------------- weight prep -----------------------------------
__global__ void k_prep(const float* __restrict__ W_in, const float* __restrict__ W_out,
                       const float* __restrict__ Ggate, const float* __restrict__ Gcand,
                       const float* __restrict__ w2,
                       const float* __restrict__ b_in, const float* __restrict__ b_out,
                       __nv_bfloat16* __restrict__ whi, __nv_bfloat16* __restrict__ wlo,
                       float* __restrict__ bio){
  int i = blockIdx.x*256 + threadIdx.x;
  if (i < 172032){
    float v = 0.f;
    if (i < 32768){
      int n = i>>7, k = i&127;
      if (k < 100) v = (n < 100) ? W_in[k*100+n] : W_out[k*100+(n-100)];
    } else if (i < 114688){
      int j = i-32768; int n = j/320, k = j - n*320;
      if (k < 300) v = Ggate[k*200+n];
    } else if (i < 155648){
      int j = i-114688; int n = j/320, k = j - n*320;
      if (k < 300) v = Gcand[k*100+n];
    } else {
      int j = i-155648; int n = j>>7, k = j&127;
      if (k < 100) v = w2[k*100+n];
    }
    __nv_bfloat16 h = __float2bfloat16(v);
    whi[i] = h;
    wlo[i] = __float2bfloat16(v - __bfloat162float(h));
  } else if (i < 172232){
    int j = i-172032;
    bio[j] = (j < 100) ? b_in[j] : b_out[j-100];
  }
}

// --------------------------- gather (float4): h -> z[:,200:300] ------------
__global__ void k_gather(const float* __restrict__ emb, const int* __restrict__ item,
                         float* __restrict__ z){
  int i = blockIdx.x*256 + threadIdx.x;
  if (i >= BT*25) return;
  int row = i/25, q = i - row*25;
  const float4 v = *(const float4*)(emb + (size_t)__ldg(&item[row])*DIM + q*4);
  *(float4*)(z + (size_t)row*300 + 200 + q*4) = v;
}

// --------------------------- adjacency einsums on tensor cores -------------
// A tiles: adj 64x64 (t x s) hi/lo inline-split; B tiles: hio^T 128x64 (d x s)
// hi/lo copied from pre-split bf16 producer. stride 72 -> conflict-free.
#define AS 72
#define ADJ_AIH 0
#define ADJ_AIL (64*AS)
#define ADJ_AOH (2*64*AS)
#define ADJ_AOL (3*64*AS)
#define ADJ_B0  (4*64*AS)
#define ADJ_BIH (ADJ_B0)
#define ADJ_BIL (ADJ_B0 + 128*AS)
#define ADJ_BOH (ADJ_B0 + 2*128*AS)
#define ADJ_BOL (ADJ_B0 + 3*128*AS)
#define ADJ_SMEM_UNITS (4*64*AS + 4*128*AS)
#define ADJ_SMEM_BYTES (ADJ_SMEM_UNITS*2)

__global__ void __launch_bounds__(256, 2) k_adj_tc(
    const float* __restrict__ adj_in, const float* __restrict__ adj_out,
    const __nv_bfloat16* __restrict__ hioh, const __nv_bfloat16* __restrict__ hiol,
    float* __restrict__ z){
  extern __shared__ __nv_bfloat16 sma[];
  int b = blockIdx.x, tid = threadIdx.x;

  // zero-fill all tiles (padding rows/cols must be 0)
  for (int i = tid; i < ADJ_SMEM_UNITS/8; i += 256)
    ((uint4*)sma)[i] = make_uint4(0,0,0,0);
  __syncthreads();

  // adj staging: float2 loads + inline split (2 x 1250 pairs)
  for (int i = tid; i < 1250; i += 256){
    int t = i/25, sp = (i - t*25)*2;
    float2 vi = *(const float2*)(adj_in  + (size_t)b*2500 + t*TSEQ + sp);
    float2 vo = *(const float2*)(adj_out + (size_t)b*2500 + t*TSEQ + sp);
    __nv_bfloat16 h, l;
    split1(vi.x, h, l); sma[ADJ_AIH + t*AS + sp] = h;   sma[ADJ_AIL + t*AS + sp] = l;
    split1(vi.y, h, l); sma[ADJ_AIH + t*AS + sp+1] = h; sma[ADJ_AIL + t*AS + sp+1] = l;
    split1(vo.x, h, l); sma[ADJ_AOH + t*AS + sp] = h;   sma[ADJ_AOL + t*AS + sp] = l;
    split1(vo.y, h, l); sma[ADJ_AOH + t*AS + sp+1] = h; sma[ADJ_AOL + t*AS + sp+1] = l;
  }
  // hio transposed copy (pre-split bf16, no conversion)
  for (int i = tid; i < 5000; i += 256){
    int s = i/100, dp = i - s*100, d = dp*2;
    uint32_t vh = *(const uint32_t*)(hioh + (size_t)(b*TSEQ+s)*200 + d);
    uint32_t vl = *(const uint32_t*)(hiol + (size_t)(b*TSEQ+s)*200 + d);
    int base = (d < 100) ? ADJ_BIH : ADJ_BOH;
    int basl = (d < 100) ? ADJ_BIL : ADJ_BOL;
    int dd = (d < 100) ? d : d-100;
    sma[base + dd*AS + s]     = __ushort_as_bfloat16((unsigned short)(vh & 0xffff));
    sma[base + (dd+1)*AS + s] = __ushort_as_bfloat16((unsigned short)(vh >> 16));
    sma[basl + dd*AS + s]     = __ushort_as_bfloat16((unsigned short)(vl & 0xffff));
    sma[basl + (dd+1)*AS + s] = __ushort_as_bfloat16((unsigned short)(vl >> 16));
  }
  __syncthreads();

  int wid = tid>>5, lane = tid&31;
  int e  = wid>>2;
  int n0 = (wid&3)*32;
  int qr = lane>>2, qc = (lane&3)*2;

  const __nv_bfloat16* Ah = sma + (e ? ADJ_AOH : ADJ_AIH);
  const __nv_bfloat16* Al = sma + (e ? ADJ_AOL : ADJ_AIL);
  const __nv_bfloat16* Bh = sma + (e ? ADJ_BOH : ADJ_BIH);
  const __nv_bfloat16* Bl = sma + (e ? ADJ_BOL : ADJ_BIL);

  float acc[4][4][4];
  #pragma unroll
  for (int mt=0;mt<4;mt++)
    #pragma unroll
    for (int nt=0;nt<4;nt++)
      #pragma unroll
      for (int j=0;j<4;j++) acc[mt][nt][j]=0.f;

  #pragma unroll
  for (int ks=0; ks<4; ks++){
    int kk = ks*16 + qc;
    uint32_t ah[4][4], al[4][4];
    #pragma unroll
    for (int mt=0; mt<4; mt++){
      int r = mt*16 + qr;
      ah[mt][0]=lds32(Ah + r*AS + kk);     ah[mt][1]=lds32(Ah + (r+8)*AS + kk);
      ah[mt][2]=lds32(Ah + r*AS + kk+8);   ah[mt][3]=lds32(Ah + (r+8)*AS + kk+8);
      al[mt][0]=lds32(Al + r*AS + kk);     al[mt][1]=lds32(Al + (r+8)*AS + kk);
      al[mt][2]=lds32(Al + r*AS + kk+8);   al[mt][3]=lds32(Al + (r+8)*AS + kk+8);
    }
    #pragma unroll
    for (int nt=0; nt<4; nt++){
      int n = n0 + nt*8 + qr;
      uint32_t bh0 = lds32(Bh + n*AS + kk), bh1 = lds32(Bh + n*AS + kk+8);
      uint32_t bl0 = lds32(Bl + n*AS + kk), bl1 = lds32(Bl + n*AS + kk+8);
      #pragma unroll
      for (int mt=0; mt<4; mt++){
        mma16816(acc[mt][nt], ah[mt][0],ah[mt][1],ah[mt][2],ah[mt][3], bh0,bh1);
        mma16816(acc[mt][nt], al[mt][0],al[mt][1],al[mt][2],al[mt][3], bh0,bh1);
        mma16816(acc[mt][nt], ah[mt][0],ah[mt][1],ah[mt][2],ah[mt][3], bl0,bl1);
      }
    }
  }

  int cb = e*100;
  #pragma unroll
  for (int mt=0; mt<4; mt++){
    int t0 = mt*16 + qr;
    #pragma unroll
    for (int nt=0; nt<4; nt++){
      int d = n0 + nt*8 + qc;
      if (d+1 < 100){
        if (t0 < TSEQ){
          float* p = z + (size_t)(b*TSEQ+t0)*300 + cb + d;
          p[0] = acc[mt][nt][0]; p[1] = acc[mt][nt][1];
        }
        if (t0+8 < TSEQ){
          float* p = z + (size_t)(b*TSEQ+t0+8)*300 + cb + d;
          p[0] = acc[mt][nt][2]; p[1] = acc[mt][nt][3];
        }
      }
    }
  }
}

// --------------------------- small FFMA SGEMM ------------------------------
__global__ void k_sgemm(const float* __restrict__ A, const float* __restrict__ Bm,
                        const float* __restrict__ bias, float* __restrict__ C,
                        int M, int N, int K, int act){
  __shared__ float As[16][65];
  __shared__ float Bs[16][65];
  int tid = threadIdx.x;
  int tx = tid & 15, ty = tid >> 4;
  int m0 = blockIdx.y*64, n0 = blockIdx.x*64;
  float acc[4][4] = {};
  for (int k0=0;k0<K;k0+=16){
    for (int idx=tid; idx<1024; idx+=256){
      int m = idx>>4, k = idx&15;
      As[k][m] = (k0+k < K) ? A[(size_t)(m0+m)*K + k0+k] : 0.f;
    }
    for (int idx=tid; idx<1024; idx+=256){
      int k = idx>>6, n = idx&63;
      Bs[k][n] = (k0+k < K && n0+n < N) ? Bm[(size_t)(k0+k)*N + n0+n] : 0.f;
    }
    __syncthreads();
    #pragma unroll
    for (int kk=0;kk<16;kk++){
      float a[4], bb[4];
      #pragma unroll
      for (int i=0;i<4;i++) a[i] = As[kk][ty+16*i];
      #pragma unroll
      for (int j=0;j<4;j++) bb[j] = Bs[kk][tx+16*j];
      #pragma unroll
      for (int i=0;i<4;i++)
        #pragma unroll
        for (int j=0;j<4;j++)
          acc[i][j] += a[i]*bb[j];
    }
    __syncthreads();
  }
  #pragma unroll
  for (int j=0;j<4;j++){
    int n = n0 + tx + 16*j;
    if (n >= N) continue;
    float bv = bias ? bias[n] : 0.f;
    #pragma unroll
    for (int i=0;i<4;i++){
      int m = m0 + ty + 16*i;
      float v = acc[i][j] + bv;
      if (act==1)      v = sigmoidf_(v);
      else if (act==2) v = tanhf(v);
      C[(size_t)m*N + n] = v;
    }
  }
}

// --------------------------- seq_h / last_h gather (float4) ----------------
__global__ void k_seqprep(const float* __restrict__ mask, const int* __restrict__ alias,
                          const float* __restrict__ remb,
                          float* __restrict__ seqh, float* __restrict__ lasth){
  __shared__ int al[TSEQ];
  __shared__ int lid_s;
  int b = blockIdx.x, tid = threadIdx.x;   // 256 threads
  if (tid < TSEQ) al[tid] = alias[b*TSEQ+tid];
  __syncthreads();
  if (tid == 0){
    float s = 0.f;
    for (int t=0;t<TSEQ;t++) s += mask[b*TSEQ+t];
    int r = (int)(s + 0.5f) - 1;
    if (r < 0) r = 0; if (r >= TSEQ) r = TSEQ-1;
    lid_s = al[r];
  }
  __syncthreads();
  for (int i=tid;i<TSEQ*25;i+=256){
    int t = i/25, q = i - t*25;
    *(float4*)(seqh + (size_t)(b*TSEQ+t)*DIM + q*4) =
      *(const float4*)(remb + (size_t)(b*TSEQ + al[t])*DIM + q*4);
  }
  if (tid < 25)
    *(float4*)(lasth + b*DIM + tid*4) =
      *(const float4*)(remb + (size_t)(b*TSEQ + lid_s)*DIM + tid*4);
}

// --------------------------- attention readout (lastT fused) ---------------
__global__ void k_attn(const float* __restrict__ lasth, const float* __restrict__ w1,
                       const float* __restrict__ seq,
                       const float* __restrict__ seqh, const float* __restrict__ nb,
                       const float* __restrict__ v, const float* __restrict__ mask,
                       float* __restrict__ ma){
  __shared__ float coef[TSEQ], lh[DIM], ls[DIM], vs[DIM], bs[DIM];
  int b = blockIdx.x, tid = threadIdx.x;
  if (tid < DIM){ lh[tid]=lasth[b*DIM+tid]; vs[tid]=v[tid]; bs[tid]=nb[tid]; }
  __syncthreads();
  // ls = lasth @ w1 (100x100), coalesced across tid
  if (tid < DIM){
    float s = 0.f;
    #pragma unroll 4
    for (int k=0;k<DIM;k++) s += lh[k]*__ldg(&w1[k*DIM+tid]);
    ls[tid] = s;
  }
  __syncthreads();
  int w = tid >> 5, lane = tid & 31;
  for (int t=w; t<TSEQ; t+=8){
    const float* srow = seq + (size_t)(b*TSEQ+t)*DIM;
    float p = 0.f;
    for (int j=lane; j<DIM; j+=32){
      float mv = sigmoidf_(ls[j]+srow[j]+bs[j]);
      p += mv*vs[j];
    }
    #pragma unroll
    for (int o=16;o;o>>=1) p += __shfl_xor_sync(0xffffffffu, p, o);
    if (lane==0) coef[t] = p * mask[b*TSEQ+t];
  }
  __syncthreads();
  if (tid < DIM){
    float s = 0.f;
    #pragma unroll
    for (int t=0;t<TSEQ;t++) s += coef[t]*seqh[(size_t)(b*TSEQ+t)*DIM+tid];
    ma[b*200+tid]       = s;
    ma[b*200+100+tid]   = ls[tid];
  }
}

// --------------------------- generic tc GEMM (inline A split) --------------
// emode 0 none, 1 sigmoid, 3 GRU fuse, 4 write bf16 hi/lo
#define LS2 72
#define GEMM_SMEM (4*128*LS2*2)

__global__ void __launch_bounds__(256, 2) k_gemm_tc(
    const float* __restrict__ A, const float* __restrict__ Gt,
    const __nv_bfloat16* __restrict__ Whi, const __nv_bfloat16* __restrict__ Wlo,
    const float* __restrict__ bias, float* __restrict__ C,
    __nv_bfloat16* __restrict__ Cbh, __nv_bfloat16* __restrict__ Cbl,
    int Astride, int Ka, int Kp, int Nact, int amode, int emode){
  extern __shared__ __nv_bfloat16 smg[];
  __nv_bfloat16* sAh = smg;
  __nv_bfloat16* sAl = smg + 128*LS2;
  __nv_bfloat16* sWh = smg + 2*128*LS2;
  __nv_bfloat16* sWl = smg + 3*128*LS2;
  int tid = threadIdx.x;
  int n0 = blockIdx.x*128, y0 = blockIdx.y*128;
  int wid = tid>>5, lane = tid&31;
  int wm = wid&3, wn = wid>>2;
  int qr = lane>>2, qc = (lane&3)*2;

  float acc[2][8][4];
  #pragma unroll
  for (int mt=0;mt<2;mt++)
    #pragma unroll
    for (int nt=0;nt<8;nt++)
      #pragma unroll
      for (int j=0;j<4;j++) acc[mt][nt][j]=0.f;

  int nchunk = Kp >> 6;
  for (int kc=0; kc<nchunk; kc++){
    #pragma unroll
    for (int s=0;s<8;s++){
      int idx = s*256+tid;
      int row = idx>>4, q = idx&15;
      int col = kc*64 + q*4;
      float4 v = make_float4(0.f,0.f,0.f,0.f);
      if (amode == 0){
        if (col < Ka) v = *(const float4*)(A + (size_t)(y0+row)*Astride + col);
      } else {
        if (col < 200) v = *(const float4*)(A + (size_t)(y0+row)*300 + col);
        else if (col < 300){
          float4 zv = *(const float4*)(A + (size_t)(y0+row)*300 + col);
          float4 gv = *(const float4*)(Gt + (size_t)(y0+row)*200 + (col-200));
          v = make_float4(zv.x*gv.x, zv.y*gv.y, zv.z*gv.z, zv.w*gv.w);
        }
      }
      uint2 hi, lo; split4(v, hi, lo);
      *(uint2*)(sAh + row*LS2 + q*4) = hi;
      *(uint2*)(sAl + row*LS2 + q*4) = lo;
    }
    #pragma unroll
    for (int s=0;s<4;s++){
      int idx = s*256+tid;
      int row = idx>>3, c8 = idx&7;
      size_t g = (size_t)(n0+row)*Kp + kc*64 + c8*8;
      *(uint4*)(sWh + row*LS2 + c8*8) = *(const uint4*)(Whi + g);
      *(uint4*)(sWl + row*LS2 + c8*8) = *(const uint4*)(Wlo + g);
    }
    __syncthreads();
    #pragma unroll
    for (int ks=0; ks<4; ks++){
      int kk = ks*16 + qc;
      uint32_t ah[2][4], al[2][4];
      #pragma unroll
      for (int mt=0; mt<2; mt++){
        int r = wm*32 + mt*16 + qr;
        const __nv_bfloat16* p0h = sAh + r*LS2;
        const __nv_bfloat16* p1h = sAh + (r+8)*LS2;
        const __nv_bfloat16* p0l = sAl + r*LS2;
        const __nv_bfloat16* p1l = sAl + (r+8)*LS2;
        ah[mt][0]=lds32(p0h+kk); ah[mt][1]=lds32(p1h+kk);
        ah[mt][2]=lds32(p0h+kk+8); ah[mt][3]=lds32(p1h+kk+8);
        al[mt][0]=lds32(p0l+kk); al[mt][1]=lds32(p1l+kk);
        al[mt][2]=lds32(p0l+kk+8); al[mt][3]=lds32(p1l+kk+8);
      }
      #pragma unroll
      for (int nt=0; nt<8; nt++){
        int n = wn*64 + nt*8 + qr;
        const __nv_bfloat16* pbh = sWh + n*LS2 + kk;
        const __nv_bfloat16* pbl = sWl + n*LS2 + kk;
        uint32_t bh0 = lds32(pbh), bh1 = lds32(pbh+8);
        uint32_t bl0 = lds32(pbl), bl1 = lds32(pbl+8);
        #pragma unroll
        for (int mt=0; mt<2; mt++){
          mma16816(acc[mt][nt], ah[mt][0],ah[mt][1],ah[mt][2],ah[mt][3], bh0,bh1);
          mma16816(acc[mt][nt], al[mt][0],al[mt][1],al[mt][2],al[mt][3], bh0,bh1);
          mma16816(acc[mt][nt], ah[mt][0],ah[mt][1],ah[mt][2],ah[mt][3], bl0,bl1);
        }
      }
    }
    __syncthreads();
  }

  #pragma unroll
  for (int mt=0; mt<2; mt++){
    int y = y0 + wm*32 + mt*16 + qr;
    #pragma unroll
    for (int nt=0; nt<8; nt++){
      #pragma unroll
      for (int half=0; half<2; half++){
        int nn = n0 + wn*64 + nt*8 + qc + half;
        if (nn >= Nact) continue;
        float bv = bias ? bias[nn] : 0.f;
        float v0 = acc[mt][nt][half]   + bv;
        float v1 = acc[mt][nt][2+half] + bv;
        if (emode==1){ v0 = sigmoidf_(v0); v1 = sigmoidf_(v1); }
        else if (emode==3){
          v0 = tanhf(v0); v1 = tanhf(v1);
          float u0 = Gt[(size_t)y*200 + 100 + nn];
          float u1 = Gt[(size_t)(y+8)*200 + 100 + nn];
          float h0 = A[(size_t)y*300 + 200 + nn];
          float h1 = A[(size_t)(y+8)*300 + 200 + nn];
          v0 = u0*h0 + (1.f-u0)*v0;
          v1 = u1*h1 + (1.f-u1)*v1;
        }
        if (emode==4){
          __nv_bfloat16 h, l;
          split1(v0, h, l); Cbh[(size_t)y*Nact + nn] = h; Cbl[(size_t)y*Nact + nn] = l;
          split1(v1, h, l); Cbh[(size_t)(y+8)*Nact + nn] = h; Cbl[(size_t)(y+8)*Nact + nn] = l;
        } else {
          C[(size_t)y*Nact + nn] = v0;
          C[(size_t)(y+8)*Nact + nn] = v1;
        }
      }
    }
  }
}

// --------------------------- logits GEMM (inline both operands, R8) --------
#define LOGITS_SMEM (4*128*LS2*2)

__global__ void __launch_bounds__(256, 2) k_logits_mma(
    const float* __restrict__ emb, const float* __restrict__ y1,
    float* __restrict__ out){
  extern __shared__ __nv_bfloat16 smb[];
  __nv_bfloat16* sYh = smb;
  __nv_bfloat16* sYl = smb + 128*LS2;
  __nv_bfloat16* sEh = smb + 2*128*LS2;
  __nv_bfloat16* sEl = smb + 3*128*LS2;

  int tid = threadIdx.x;
  int e0 = blockIdx.x*128;
  int y0 = blockIdx.y*128;
  int wid = tid>>5, lane = tid&31;
  int wm = wid&3, wn = wid>>2;
  int qr = lane>>2, qc = (lane&3)*2;

  float acc[2][8][4];
  #pragma unroll
  for (int mt=0;mt<2;mt++)
    #pragma unroll
    for (int nt=0;nt<8;nt++)
      #pragma unroll
      for (int j=0;j<4;j++) acc[mt][nt][j] = 0.f;

  #pragma unroll
  for (int kc=0; kc<2; kc++){
    #pragma unroll
    for (int s=0;s<8;s++){
      int idx = s*256+tid;
      int row = idx>>4, q = idx&15;
      int col = kc*64 + q*4;
      float4 vy = make_float4(0.f,0.f,0.f,0.f);
      if (col < 100) vy = *(const float4*)(y1 + (size_t)(y0+row)*100 + col);
      uint2 hi, lo; split4(vy, hi, lo);
      *(uint2*)(sYh + row*LS2 + q*4) = hi;
      *(uint2*)(sYl + row*LS2 + q*4) = lo;
      float4 ve = make_float4(0.f,0.f,0.f,0.f);
      int er = e0 + row;
      if (col < 100 && er < NOUT) ve = *(const float4*)(emb + (size_t)(er+1)*100 + col);
      split4(ve, hi, lo);
      *(uint2*)(sEh + row*LS2 + q*4) = hi;
      *(uint2*)(sEl + row*LS2 + q*4) = lo;
    }
    __syncthreads();
    #pragma unroll
    for (int ks=0; ks<4; ks++){
      int kk = ks*16 + qc;
      uint32_t ah[2][4], al[2][4];
      #pragma unroll
      for (int mt=0; mt<2; mt++){
        int r = wm*32 + mt*16 + qr;
        const __nv_bfloat16* p0h = sYh + r*LS2;
        const __nv_bfloat16* p1h = sYh + (r+8)*LS2;
        const __nv_bfloat16* p0l = sYl + r*LS2;
        const __nv_bfloat16* p1l = sYl + (r+8)*LS2;
        ah[mt][0]=lds32(p0h+kk); ah[mt][1]=lds32(p1h+kk);
        ah[mt][2]=lds32(p0h+kk+8); ah[mt][3]=lds32(p1h+kk+8);
        al[mt][0]=lds32(p0l+kk); al[mt][1]=lds32(p1l+kk);
        al[mt][2]=lds32(p0l+kk+8); al[mt][3]=lds32(p1l+kk+8);
      }
      #pragma unroll
      for (int nt=0; nt<8; nt++){
        int n = wn*64 + nt*8 + qr;
        const __nv_bfloat16* pbh = sEh + n*LS2 + kk;
        const __nv_bfloat16* pbl = sEl + n*LS2 + kk;
        uint32_t bh0 = lds32(pbh), bh1 = lds32(pbh+8);
        uint32_t bl0 = lds32(pbl), bl1 = lds32(pbl+8);
        #pragma unroll
        for (int mt=0; mt<2; mt++){
          mma16816(acc[mt][nt], ah[mt][0],ah[mt][1],ah[mt][2],ah[mt][3], bh0,bh1);
          mma16816(acc[mt][nt], al[mt][0],al[mt][1],al[mt][2],al[mt][3], bh0,bh1);
          mma16816(acc[mt][nt], ah[mt][0],ah[mt][1],ah[mt][2],ah[mt][3], bl0,bl1);
        }
      }
    }
    __syncthreads();
  }

  #pragma unroll
  for (int mt=0; mt<2; mt++){
    int y = y0 + wm*32 + mt*16 + qr;
    #pragma unroll
    for (int nt=0; nt<8; nt++){
      int e = e0 + wn*64 + nt*8 + qc;
      float* po = out + (size_t)y*NOUT + e;
      if (e   < NOUT){ po[0] = acc[mt][nt][0]; po[(size_t)8*NOUT] = acc[mt][nt][2]; }
      if (e+1 < NOUT){ po[1] = acc[mt][nt][1]; po[(size_t)8*NOUT+1] = acc[mt][nt][3]; }
    }
  }
}

// ---------------------------------------------------------------------------
extern "C" void kernel_launch(void* const* d_in, const int* in_sizes, int n_in,
                              void* d_out, int out_size){
  const float* adj_in  = (const float*)d_in[0];
  const float* adj_out = (const float*)d_in[1];
  const float* maskp   = (const float*)d_in[2];
  const int*   item    = (const int*)d_in[3];
  const int*   alias   = (const int*)d_in[4];
  int o = (n_in >= 20 && in_sizes[5] == 1) ? 6 : 5;
  const float* emb   = (const float*)d_in[o+0];
  const float* W_in  = (const float*)d_in[o+1];
  const float* b_in  = (const float*)d_in[o+2];
  const float* W_out = (const float*)d_in[o+3];
  const float* b_out = (const float*)d_in[o+4];
  const float* Ggate = (const float*)d_in[o+5];
  const float* gb    = (const float*)d_in[o+6];
  const float* Gcand = (const float*)d_in[o+7];
  const float* cb    = (const float*)d_in[o+8];
  const float* w1    = (const float*)d_in[o+9];
  const float* w2    = (const float*)d_in[o+10];
  const float* vv    = (const float*)d_in[o+11];
  const float* nb    = (const float*)d_in[o+12];
  const float* Bmat  = (const float*)d_in[o+13];
  float* out = (float*)d_out;
  (void)out_size;

  float* sc = nullptr;
  cudaGetSymbolAddress((void**)&sc, g_scratch);
  __nv_bfloat16 *whi=nullptr, *wlo=nullptr, *hiohi=nullptr, *hiolo=nullptr;
  cudaGetSymbolAddress((void**)&whi, g_whi);
  cudaGetSymbolAddress((void**)&wlo, g_wlo);
  cudaGetSymbolAddress((void**)&hiohi, g_hiohi);
  cudaGetSymbolAddress((void**)&hiolo, g_hiolo);

  float* z     = sc + OFF_Z;
  float* gates = sc + OFF_GATES;
  float* remb  = sc + OFF_REMB;
  float* seqh  = sc + OFF_SEQH;
  float* seq   = sc + OFF_SEQ;
  float* lasth = sc + OFF_LASTH;
  float* ma    = sc + OFF_MA;
  float* y1    = sc + OFF_Y1;
  float* bio   = sc + OFF_BIO;

  cudaFuncSetAttribute(k_adj_tc, cudaFuncAttributeMaxDynamicSharedMemorySize, ADJ_SMEM_BYTES);
  cudaFuncSetAttribute(k_gemm_tc, cudaFuncAttributeMaxDynamicSharedMemorySize, GEMM_SMEM);
  cudaFuncSetAttribute(k_logits_mma, cudaFuncAttributeMaxDynamicSharedMemorySize, LOGITS_SMEM);

  k_prep<<<(172232+255)/256,256>>>(W_in, W_out, Ggate, Gcand, w2, b_in, b_out, whi, wlo, bio);
  k_gather<<<(BT*25+255)/256, 256>>>(emb, item, z);
  // hio (bf16 hi/lo) = [h@W_in+b_in, h@W_out+b_out]
  k_gemm_tc<<<dim3(2,200),256,GEMM_SMEM>>>(z+200, nullptr, whi+WO_HIO, wlo+WO_HIO,
                                           bio, nullptr, hiohi, hiolo, 300, 100, 128, 200, 0, 4);
  k_adj_tc<<<BATCH,256,ADJ_SMEM_BYTES>>>(adj_in, adj_out, hiohi, hiolo, z);
  k_gemm_tc<<<dim3(2,200),256,GEMM_SMEM>>>(z, nullptr, whi+WO_GATE, wlo+WO_GATE,
                                           gb, gates, nullptr, nullptr, 300, 300, 320, 200, 0, 1);
  k_gemm_tc<<<dim3(1,200),256,GEMM_SMEM>>>(z, gates, whi+WO_CAND, wlo+WO_CAND,
                                           cb, remb, nullptr, nullptr, 300, 300, 320, 100, 1, 3);
  k_seqprep<<<BATCH,256>>>(maskp, alias, remb, seqh, lasth);
  k_gemm_tc<<<dim3(1,200),256,GEMM_SMEM>>>(seqh, nullptr, whi+WO_SEQ, wlo+WO_SEQ,
                                           nullptr, seq, nullptr, nullptr, 100, 100, 128, 100, 0, 0);
  k_attn<<<BATCH,256>>>(lasth, w1, seq, seqh, nb, vv, maskp, ma);
  k_sgemm<<<dim3(2,8),256>>>(ma, Bmat, nullptr, y1, 512, DIM, 200, 0);
  k_logits_mma<<<dim3(EPAD/128, 4), 256, LOGITS_SMEM>>>(emb, y1, out);
}